// round 8
// baseline (speedup 1.0000x reference)
#include <cuda_runtime.h>
#include <math.h>

#define BB 16
#define SS 2048
#define DD 768
#define DD4 192          // DD/4
#define KW 3
#define ROW3 (DD*KW)     // 2304
#define NCHUNK 16
#define OPC (DD/NCHUNK)  // 48 output channels per chunk
#define CH 8             // scan chunks per batch
#define CSZ (SS/CH)      // 256 steps per chunk

// ---- scratch (no allocations allowed) ----
__device__ float  g_part[NCHUNK][ROW3];
__device__ float  g_weff[KW][DD];     // w_eff[k][d], d contiguous
__device__ float  g_beff;
__device__ float  g_r0[BB*SS];        // SoA conv partials
__device__ float  g_r1[BB*SS];
__device__ float  g_r2[BB*SS];
__device__ float  g_wmain[BB*SS];
__device__ float  g_wspill[BB*SS];
__device__ int    g_firepos[BB*SS];   // per batch: step index of fire j
__device__ int    g_F[BB];            // number of fires per batch
__device__ double g_csum[BB*CH];      // per-chunk alpha totals
__device__ int    g_cflag[BB*CH];     // publish flags (zeroed in kA1)

// ============================================================
// kA1: partial w_eff over o-chunks.  grid (9, 16) x 256
// Also zeroes the scan-chunk flags (stream-ordered before kC).
// ============================================================
__global__ void kA1(const float* __restrict__ conv_w,
                    const float* __restrict__ lin_w) {
    int t  = blockIdx.x * blockDim.x + threadIdx.x;   // 0..2303
    if (blockIdx.x == 0 && blockIdx.y == 0 && threadIdx.x < BB * CH)
        g_cflag[threadIdx.x] = 0;
    int o0 = blockIdx.y * OPC;
    float acc = 0.f;
#pragma unroll 8
    for (int o = o0; o < o0 + OPC; ++o)
        acc += lin_w[o] * conv_w[o * ROW3 + t];
    g_part[blockIdx.y][t] = acc;
}

// kA2: combine partials (fixed order -> deterministic) + b_eff. grid 9 x 256
__global__ void kA2(const float* __restrict__ conv_b,
                    const float* __restrict__ lin_w,
                    const float* __restrict__ lin_b) {
    int t = blockIdx.x * blockDim.x + threadIdx.x;
    float s = 0.f;
#pragma unroll
    for (int c = 0; c < NCHUNK; ++c) s += g_part[c][t];
    g_weff[t % 3][t / 3] = s;

    if (blockIdx.x == 0) {
        __shared__ float red[256];
        float s2 = 0.f;
        for (int i = threadIdx.x; i < DD; i += 256)
            s2 += lin_w[i] * conv_b[i];
        red[threadIdx.x] = s2;
        __syncthreads();
        for (int st = 128; st > 0; st >>= 1) {
            if (threadIdx.x < st) red[threadIdx.x] += red[threadIdx.x + st];
            __syncthreads();
        }
        if (threadIdx.x == 0) g_beff = red[0] + lin_b[0];
    }
}

// ============================================================
// kB: r_k[b,t] = sum_d w_eff[d,k] * x[b,t,d].  One warp per row.
// grid BB*SS/8 x 256
// ============================================================
__global__ void kB(const float* __restrict__ x) {
    int row  = blockIdx.x * 8 + (threadIdx.x >> 5);   // 0..BB*SS-1
    int lane = threadIdx.x & 31;
    const float4* xr = (const float4*)(x) + (size_t)row * DD4;
    const float4* w0 = (const float4*)g_weff[0];
    const float4* w1 = (const float4*)g_weff[1];
    const float4* w2 = (const float4*)g_weff[2];
    float a0 = 0.f, a1 = 0.f, a2 = 0.f;
#pragma unroll
    for (int i = 0; i < 6; ++i) {
        int c = lane + i * 32;
        float4 xv = xr[c];
        float4 v0 = w0[c], v1 = w1[c], v2 = w2[c];
        a0 += xv.x*v0.x + xv.y*v0.y + xv.z*v0.z + xv.w*v0.w;
        a1 += xv.x*v1.x + xv.y*v1.y + xv.z*v1.z + xv.w*v1.w;
        a2 += xv.x*v2.x + xv.y*v2.y + xv.z*v2.z + xv.w*v2.w;
    }
#pragma unroll
    for (int off = 16; off > 0; off >>= 1) {
        a0 += __shfl_down_sync(0xffffffffu, a0, off);
        a1 += __shfl_down_sync(0xffffffffu, a1, off);
        a2 += __shfl_down_sync(0xffffffffu, a2, off);
    }
    if (lane == 0) {
        g_r0[row] = a0;
        g_r1[row] = a1;
        g_r2[row] = a2;
    }
}

// ============================================================
// kC: decoupled-lookback fp64 scan.  grid BB*CH x 128.
// Block = one 256-step chunk of one batch; 2 steps per thread.
// ============================================================
__global__ void kC(const int* __restrict__ lens, float* __restrict__ lens_out) {
    __shared__ double wt[4], wo[4];
    __shared__ double s_off;

    int blk  = blockIdx.x;            // b*CH + c
    int b    = blk / CH;
    int cidx = blk - b * CH;
    int tid  = threadIdx.x;           // 0..127
    int len  = lens[b];
    int base = b * SS;
    int tb   = cidx * CSZ + tid * 2;  // local step index (within batch)

    float beff = g_beff;

    // alphas for the two steps (coalesced global loads, L2-hot after kB)
    float a[2];
#pragma unroll
    for (int e = 0; e < 2; ++e) {
        int t = tb + e;
        float logit = beff + g_r1[base + t];
        if (t > 0)      logit += g_r0[base + t - 1];
        if (t < SS - 1) logit += g_r2[base + t + 1];
        float al = 1.f / (1.f + expf(-logit));
        a[e] = (t < len) ? al : 0.f;
    }

    // local fp64 pair scan (4 warps)
    double pair = (double)a[0] + (double)a[1];
    double v = pair;
    int lane = tid & 31, wid = tid >> 5;
#pragma unroll
    for (int off = 1; off < 32; off <<= 1) {
        double n = __shfl_up_sync(0xffffffffu, v, off);
        if (lane >= off) v += n;
    }
    if (lane == 31) wt[wid] = v;
    __syncthreads();
    if (tid == 0) {
        double run = 0.0;
#pragma unroll
        for (int w = 0; w < 4; ++w) { wo[w] = run; run += wt[w]; }
        // publish chunk total before lookback (no circular wait)
        g_csum[blk] = run;
        __threadfence();
        atomicExch(&g_cflag[blk], 1);
        // lookback: fixed-order sum of predecessor chunk totals
        double off = 0.0;
        for (int j = b * CH; j < blk; ++j) {
            while (atomicAdd(&g_cflag[j], 0) == 0) { }
            __threadfence();
            off += g_csum[j];
        }
        s_off = off;
    }
    __syncthreads();

    double incl  = s_off + wo[wid] + v;        // global inclusive at pair end
    double excl0 = incl - pair;

    double C0 = excl0 + (double)a[0];
    double C1 = C0 + (double)a[1];
    double Ce[2] = {excl0, C0};
    double Ci[2] = {C0, C1};

    float w1v[2], w2v[2];
#pragma unroll
    for (int e = 0; e < 2; ++e) {
        int t = tb + e;
        double fp = floor(Ce[e]);
        double fc = floor(Ci[e]);
        float af = a[e];
        float w1, w2 = 0.f;
        if (fc > fp) {                      // fire (alpha<1 => fc == fp+1)
            float aaccf = (float)(Ce[e] - fp);   // reference-style f32 aacc
            w1 = 1.0f - aaccf;
            w2 = af - w1;
            g_firepos[base + (int)fp] = t;
        } else {
            w1 = af;
        }
        w1v[e] = w1; w2v[e] = w2;
        if (t == SS - 1) {
            int F = (int)fc;                 // total fires = floor(total masked sum)
            g_F[b] = F;
            if (lens_out) lens_out[b] = (float)F;
        }
    }
    *(float2*)(g_wmain  + base + tb) = make_float2(w1v[0], w1v[1]);
    *(float2*)(g_wspill + base + tb) = make_float2(w2v[0], w2v[1]);
}

// ============================================================
// kD: output row (b,j) = segmented weighted sum, same t-order as reference.
// grid (SS, BB) x 192 threads (one float4 column per thread).
// ============================================================
__global__ void kD(const float* __restrict__ x, float* __restrict__ out) {
    int j = blockIdx.x, b = blockIdx.y;
    int i = threadIdx.x;                  // 0..191
    float4* o4 = (float4*)out + (size_t)(b * SS + j) * DD4 + i;
    int F = g_F[b];
    if (j >= F) { *o4 = make_float4(0.f, 0.f, 0.f, 0.f); return; }

    int p1 = g_firepos[b * SS + j];
    int p0 = (j == 0) ? 0 : g_firepos[b * SS + j - 1];
    const float4* x4 = (const float4*)x + (size_t)b * SS * DD4 + i;

    float4 acc = make_float4(0.f, 0.f, 0.f, 0.f);
    int t = p0;
    if (j > 0) {                          // spill a2*h from previous fire step
        float w = g_wspill[b * SS + p0];
        float4 h = __ldg(x4 + (size_t)p0 * DD4);
        acc.x = w * h.x; acc.y = w * h.y; acc.z = w * h.z; acc.w = w * h.w;
        t = p0 + 1;
    }
#pragma unroll 4
    for (; t <= p1; ++t) {                // interior a*h ... then a1*h at fire
        float w = g_wmain[b * SS + t];
        float4 h = __ldg(x4 + (size_t)t * DD4);
        acc.x += w * h.x; acc.y += w * h.y; acc.z += w * h.z; acc.w += w * h.w;
    }
    *o4 = acc;
}

// ============================================================
extern "C" void kernel_launch(void* const* d_in, const int* in_sizes, int n_in,
                              void* d_out, int out_size) {
    const float* x      = (const float*)d_in[0];   // encoder_outputs (B,S,D)
    const int*   lens   = (const int*)  d_in[1];   // encoder_lens (B,)
    const float* conv_w = (const float*)d_in[2];   // (D,D,3)
    const float* conv_b = (const float*)d_in[3];   // (D,)
    const float* lin_w  = (const float*)d_in[4];   // (1,D)
    const float* lin_b  = (const float*)d_in[5];   // (1,)
    float* out = (float*)d_out;
    float* lens_out = (out_size >= BB * SS * DD + BB) ? out + (size_t)BB * SS * DD
                                                      : nullptr;

    kA1<<<dim3(ROW3 / 256, NCHUNK), 256>>>(conv_w, lin_w);
    kA2<<<ROW3 / 256, 256>>>(conv_b, lin_w, lin_b);
    kB<<<BB * SS / 8, 256>>>(x);
    kC<<<BB * CH, 128>>>(lens, lens_out);
    kD<<<dim3(SS, BB), 192>>>(x, out);
}

// round 9
// speedup vs baseline: 1.2605x; 1.2605x over previous
#include <cuda_runtime.h>
#include <math.h>

#define BB 16
#define SS 2048
#define DD 768
#define DD4 192          // DD/4
#define KW 3
#define ROW3 (DD*KW)     // 2304
#define NCHUNK 16
#define OPC (DD/NCHUNK)  // 48 output channels per chunk

// ---- scratch (no allocations allowed; .bss-zeroed at load) ----
__device__ float  g_part[NCHUNK][ROW3];
__device__ float  g_weff[KW][DD];     // w_eff[k][d], d contiguous
__device__ float  g_beff;
__device__ float  g_r0[BB*SS];        // SoA conv partials
__device__ float  g_r1[BB*SS];
__device__ float  g_r2[BB*SS];
__device__ float  g_wmain[BB*SS];
__device__ float  g_wspill[BB*SS];
__device__ int    g_firepos[BB*SS];   // per batch: step index of fire j
__device__ int    g_F[BB];            // number of fires per batch

// ============================================================
// kA1: partial w_eff over o-chunks.  grid (9, 16) x 256
// conv_w layout (O, I, K): element (o,d,k) at o*ROW3 + d*3 + k
// ============================================================
__global__ void kA1(const float* __restrict__ conv_w,
                    const float* __restrict__ lin_w) {
    int t  = blockIdx.x * blockDim.x + threadIdx.x;   // 0..2303
    int o0 = blockIdx.y * OPC;
    float acc = 0.f;
#pragma unroll 8
    for (int o = o0; o < o0 + OPC; ++o)
        acc += lin_w[o] * conv_w[o * ROW3 + t];
    g_part[blockIdx.y][t] = acc;
}

// kA2: combine partials (fixed order -> deterministic) + b_eff. grid 9 x 256
__global__ void kA2(const float* __restrict__ conv_b,
                    const float* __restrict__ lin_w,
                    const float* __restrict__ lin_b) {
    int t = blockIdx.x * blockDim.x + threadIdx.x;
    float s = 0.f;
#pragma unroll
    for (int c = 0; c < NCHUNK; ++c) s += g_part[c][t];
    g_weff[t % 3][t / 3] = s;

    if (blockIdx.x == 0) {
        __shared__ float red[256];
        float s2 = 0.f;
        for (int i = threadIdx.x; i < DD; i += 256)
            s2 += lin_w[i] * conv_b[i];
        red[threadIdx.x] = s2;
        __syncthreads();
        for (int st = 128; st > 0; st >>= 1) {
            if (threadIdx.x < st) red[threadIdx.x] += red[threadIdx.x + st];
            __syncthreads();
        }
        if (threadIdx.x == 0) g_beff = red[0] + lin_b[0];
    }
}

// ============================================================
// kB: r_k[b,t] = sum_d w_eff[d,k] * x[b,t,d].  One warp per row.
// Rows with t > len[b] are dead (alpha masked to 0 downstream;
// r2[len] is the last value any live logit reads) -> early-out.
// grid BB*SS/8 x 256
// ============================================================
__global__ void kB(const float* __restrict__ x, const int* __restrict__ lens) {
    int row  = blockIdx.x * 8 + (threadIdx.x >> 5);   // 0..BB*SS-1
    int lane = threadIdx.x & 31;
    int b = row >> 11;                 // row / SS
    int t = row & (SS - 1);
    if (t > __ldg(lens + b)) return;   // dead row: g_r stays 0 (.bss) -> deterministic

    const float4* xr = (const float4*)(x) + (size_t)row * DD4;
    const float4* w0 = (const float4*)g_weff[0];
    const float4* w1 = (const float4*)g_weff[1];
    const float4* w2 = (const float4*)g_weff[2];
    float a0 = 0.f, a1 = 0.f, a2 = 0.f;
#pragma unroll
    for (int i = 0; i < 6; ++i) {
        int c = lane + i * 32;
        float4 xv = xr[c];
        float4 v0 = w0[c], v1 = w1[c], v2 = w2[c];
        a0 += xv.x*v0.x + xv.y*v0.y + xv.z*v0.z + xv.w*v0.w;
        a1 += xv.x*v1.x + xv.y*v1.y + xv.z*v1.z + xv.w*v1.w;
        a2 += xv.x*v2.x + xv.y*v2.y + xv.z*v2.z + xv.w*v2.w;
    }
#pragma unroll
    for (int off = 16; off > 0; off >>= 1) {
        a0 += __shfl_down_sync(0xffffffffu, a0, off);
        a1 += __shfl_down_sync(0xffffffffu, a1, off);
        a2 += __shfl_down_sync(0xffffffffu, a2, off);
    }
    if (lane == 0) {
        g_r0[row] = a0;
        g_r1[row] = a1;
        g_r2[row] = a2;
    }
}

// ============================================================
// kC: per-batch sigmoid + fp64 pair scan (R5 topology, best measured).
// Dead steps (t >= len) skip loads/expf/stores and contribute zeros.
// grid BB x 1024, 2 timesteps per thread.
// ============================================================
__global__ void kC(const int* __restrict__ lens, float* __restrict__ lens_out) {
    __shared__ double wt[32], wo[32];

    int b    = blockIdx.x;
    int tid  = threadIdx.x;
    int len  = lens[b];
    int base = b * SS;
    int tbase = tid * 2;

    float a[2] = {0.f, 0.f};
    if (tbase < len) {                 // at least lane 0 live
        float beff = g_beff;
#pragma unroll
        for (int e = 0; e < 2; ++e) {
            int t = tbase + e;
            if (t < len) {
                float logit = beff + g_r1[base + t];
                if (t > 0)      logit += g_r0[base + t - 1];
                if (t < SS - 1) logit += g_r2[base + t + 1];
                a[e] = 1.f / (1.f + expf(-logit));
            }
        }
    }

    double pair = (double)a[0] + (double)a[1];
    double v = pair;
    int lane = tid & 31, wid = tid >> 5;
#pragma unroll
    for (int off = 1; off < 32; off <<= 1) {
        double n = __shfl_up_sync(0xffffffffu, v, off);
        if (lane >= off) v += n;
    }
    if (lane == 31) wt[wid] = v;
    __syncthreads();
    if (wid == 0) {
        double u = wt[lane];
#pragma unroll
        for (int off = 1; off < 32; off <<= 1) {
            double n = __shfl_up_sync(0xffffffffu, u, off);
            if (lane >= off) u += n;
        }
        wo[lane] = u - wt[lane];   // exclusive warp offset
    }
    __syncthreads();
    double incl  = v + wo[wid];
    double excl0 = incl - pair;

    // total fires: floor of block total (zeros beyond len don't change it)
    if (tid == 1023) {
        int F = (int)floor(incl);
        g_F[b] = F;
        if (lens_out) lens_out[b] = (float)F;
    }

    if (tbase >= len) return;          // dead pair: nothing downstream reads it

    double C0 = excl0 + (double)a[0];
    double C1 = C0 + (double)a[1];
    double Ce[2] = {excl0, C0};
    double Ci[2] = {C0, C1};

    float w1v[2], w2v[2];
#pragma unroll
    for (int e = 0; e < 2; ++e) {
        int t = tbase + e;
        double fp = floor(Ce[e]);
        double fc = floor(Ci[e]);
        float af = a[e];
        float w1, w2 = 0.f;
        if (fc > fp) {                      // fire (alpha<1 => fc == fp+1)
            float aaccf = (float)(Ce[e] - fp);   // reference-style f32 aacc
            w1 = 1.0f - aaccf;
            w2 = af - w1;
            g_firepos[base + (int)fp] = t;
        } else {
            w1 = af;
        }
        w1v[e] = w1; w2v[e] = w2;
    }
    *(float2*)(g_wmain  + base + tbase) = make_float2(w1v[0], w1v[1]);
    *(float2*)(g_wspill + base + tbase) = make_float2(w2v[0], w2v[1]);
}

// ============================================================
// kD: output row (b,j) = segmented weighted sum, same t-order as reference.
// grid (SS, BB) x 192 threads (one float4 column per thread).
// ============================================================
__global__ void kD(const float* __restrict__ x, float* __restrict__ out) {
    int j = blockIdx.x, b = blockIdx.y;
    int i = threadIdx.x;                  // 0..191
    float4* o4 = (float4*)out + (size_t)(b * SS + j) * DD4 + i;
    int F = g_F[b];
    if (j >= F) { *o4 = make_float4(0.f, 0.f, 0.f, 0.f); return; }

    int p1 = g_firepos[b * SS + j];
    int p0 = (j == 0) ? 0 : g_firepos[b * SS + j - 1];
    const float4* x4 = (const float4*)x + (size_t)b * SS * DD4 + i;

    float4 acc = make_float4(0.f, 0.f, 0.f, 0.f);
    int t = p0;
    if (j > 0) {                          // spill a2*h from previous fire step
        float w = g_wspill[b * SS + p0];
        float4 h = __ldg(x4 + (size_t)p0 * DD4);
        acc.x = w * h.x; acc.y = w * h.y; acc.z = w * h.z; acc.w = w * h.w;
        t = p0 + 1;
    }
#pragma unroll 4
    for (; t <= p1; ++t) {                // interior a*h ... then a1*h at fire
        float w = g_wmain[b * SS + t];
        float4 h = __ldg(x4 + (size_t)t * DD4);
        acc.x += w * h.x; acc.y += w * h.y; acc.z += w * h.z; acc.w += w * h.w;
    }
    *o4 = acc;
}

// ============================================================
extern "C" void kernel_launch(void* const* d_in, const int* in_sizes, int n_in,
                              void* d_out, int out_size) {
    const float* x      = (const float*)d_in[0];   // encoder_outputs (B,S,D)
    const int*   lens   = (const int*)  d_in[1];   // encoder_lens (B,)
    const float* conv_w = (const float*)d_in[2];   // (D,D,3)
    const float* conv_b = (const float*)d_in[3];   // (D,)
    const float* lin_w  = (const float*)d_in[4];   // (1,D)
    const float* lin_b  = (const float*)d_in[5];   // (1,)
    float* out = (float*)d_out;
    float* lens_out = (out_size >= BB * SS * DD + BB) ? out + (size_t)BB * SS * DD
                                                      : nullptr;

    kA1<<<dim3(ROW3 / 256, NCHUNK), 256>>>(conv_w, lin_w);
    kA2<<<ROW3 / 256, 256>>>(conv_b, lin_w, lin_b);
    kB<<<BB * SS / 8, 256>>>(x, lens);
    kC<<<BB, 1024>>>(lens, lens_out);
    kD<<<dim3(SS, BB), 192>>>(x, out);
}

// round 10
// speedup vs baseline: 1.2625x; 1.0016x over previous
#include <cuda_runtime.h>
#include <math.h>

#define BB 16
#define SS 2048
#define DD 768
#define DD4 192          // DD/4
#define KW 3
#define ROW3 (DD*KW)     // 2304
#define NCHUNK 16
#define OPC (DD/NCHUNK)  // 48 output channels per chunk
#define CH 8             // scan chunks per batch
#define CSZ (SS/CH)      // 256 steps per chunk

// ---- scratch (no allocations allowed; .bss-zeroed at load) ----
__device__ float  g_part[NCHUNK][ROW3];
__device__ float  g_weff[KW][DD];     // w_eff[k][d], d contiguous
__device__ float  g_beff;
__device__ float  g_r0[BB*SS];        // SoA conv partials
__device__ float  g_r1[BB*SS];
__device__ float  g_r2[BB*SS];
__device__ float  g_a[BB*SS];         // masked alphas
__device__ double g_csum[BB*CH];      // per-chunk alpha totals
__device__ double g_coff[BB*CH];      // exclusive chunk offsets
__device__ float  g_wmain[BB*SS];
__device__ float  g_wspill[BB*SS];
__device__ int    g_firepos[BB*SS];   // per batch: step index of fire j
__device__ int    g_F[BB];            // number of fires per batch

// ============================================================
// kA1: partial w_eff over o-chunks.  grid (9, 16) x 256
// ============================================================
__global__ void kA1(const float* __restrict__ conv_w,
                    const float* __restrict__ lin_w) {
    int t  = blockIdx.x * blockDim.x + threadIdx.x;   // 0..2303
    int o0 = blockIdx.y * OPC;
    float acc = 0.f;
#pragma unroll 8
    for (int o = o0; o < o0 + OPC; ++o)
        acc += lin_w[o] * conv_w[o * ROW3 + t];
    g_part[blockIdx.y][t] = acc;
}

// kA2: combine partials (fixed order -> deterministic) + b_eff. grid 9 x 256
__global__ void kA2(const float* __restrict__ conv_b,
                    const float* __restrict__ lin_w,
                    const float* __restrict__ lin_b) {
    int t = blockIdx.x * blockDim.x + threadIdx.x;
    float s = 0.f;
#pragma unroll
    for (int c = 0; c < NCHUNK; ++c) s += g_part[c][t];
    g_weff[t % 3][t / 3] = s;

    if (blockIdx.x == 0) {
        __shared__ float red[256];
        float s2 = 0.f;
        for (int i = threadIdx.x; i < DD; i += 256)
            s2 += lin_w[i] * conv_b[i];
        red[threadIdx.x] = s2;
        __syncthreads();
        for (int st = 128; st > 0; st >>= 1) {
            if (threadIdx.x < st) red[threadIdx.x] += red[threadIdx.x + st];
            __syncthreads();
        }
        if (threadIdx.x == 0) g_beff = red[0] + lin_b[0];
    }
}

// ============================================================
// kB: r_k[b,t] = sum_d w_eff[d,k] * x[b,t,d].  One warp per row.
// Rows with t > len[b] are dead -> early-out (g_r stays 0 from .bss).
// grid BB*SS/8 x 256
// ============================================================
__global__ void kB(const float* __restrict__ x, const int* __restrict__ lens) {
    int row  = blockIdx.x * 8 + (threadIdx.x >> 5);   // 0..BB*SS-1
    int lane = threadIdx.x & 31;
    int b = row >> 11;                 // row / SS
    int t = row & (SS - 1);
    if (t > __ldg(lens + b)) return;

    const float4* xr = (const float4*)(x) + (size_t)row * DD4;
    const float4* w0 = (const float4*)g_weff[0];
    const float4* w1 = (const float4*)g_weff[1];
    const float4* w2 = (const float4*)g_weff[2];
    float a0 = 0.f, a1 = 0.f, a2 = 0.f;
#pragma unroll
    for (int i = 0; i < 6; ++i) {
        int c = lane + i * 32;
        float4 xv = xr[c];
        float4 v0 = w0[c], v1 = w1[c], v2 = w2[c];
        a0 += xv.x*v0.x + xv.y*v0.y + xv.z*v0.z + xv.w*v0.w;
        a1 += xv.x*v1.x + xv.y*v1.y + xv.z*v1.z + xv.w*v1.w;
        a2 += xv.x*v2.x + xv.y*v2.y + xv.z*v2.z + xv.w*v2.w;
    }
#pragma unroll
    for (int off = 16; off > 0; off >>= 1) {
        a0 += __shfl_down_sync(0xffffffffu, a0, off);
        a1 += __shfl_down_sync(0xffffffffu, a1, off);
        a2 += __shfl_down_sync(0xffffffffu, a2, off);
    }
    if (lane == 0) {
        g_r0[row] = a0;
        g_r1[row] = a1;
        g_r2[row] = a2;
    }
}

// ============================================================
// kC1: alphas + per-chunk fp64 totals.  grid BB*CH x 256 (1 step/thread).
// ============================================================
__global__ void kC1(const int* __restrict__ lens) {
    __shared__ double ws[8];
    int blk = blockIdx.x;              // b*CH + c
    int b   = blk >> 3;
    int c   = blk & 7;
    int tid = threadIdx.x;             // 0..255
    int t   = c * CSZ + tid;
    int len = lens[b];
    int base = b * SS;

    float a = 0.f;
    if (t < len) {
        float logit = g_beff + g_r1[base + t];
        if (t > 0)      logit += g_r0[base + t - 1];
        if (t < SS - 1) logit += g_r2[base + t + 1];
        a = 1.f / (1.f + expf(-logit));
        g_a[base + t] = a;
    }

    double v = (double)a;
    int lane = tid & 31, wid = tid >> 5;
#pragma unroll
    for (int off = 16; off > 0; off >>= 1)
        v += __shfl_down_sync(0xffffffffu, v, off);
    if (lane == 0) ws[wid] = v;
    __syncthreads();
    if (tid == 0) {
        double s = 0.0;
#pragma unroll
        for (int w = 0; w < 8; ++w) s += ws[w];   // fixed order
        g_csum[blk] = s;
    }
}

// ============================================================
// kC2: tiny serial scan of chunk totals.  grid 1 x 32.
// ============================================================
__global__ void kC2(float* __restrict__ lens_out) {
    int b = threadIdx.x;
    if (b >= BB) return;
    double run = 0.0;
#pragma unroll
    for (int c = 0; c < CH; ++c) {
        g_coff[b * CH + c] = run;
        run += g_csum[b * CH + c];
    }
    int F = (int)floor(run);
    g_F[b] = F;
    if (lens_out) lens_out[b] = (float)F;
}

// ============================================================
// kC3: local fp64 pair scan + global offset, emit weights/firepos.
// grid BB*CH x 128 (2 steps/thread).
// ============================================================
__global__ void kC3(const int* __restrict__ lens) {
    __shared__ double wt[4], wo[4];
    int blk = blockIdx.x;
    int b   = blk >> 3;
    int cix = blk & 7;
    int tid = threadIdx.x;             // 0..127
    int len = lens[b];
    int base = b * SS;
    int tb  = cix * CSZ + tid * 2;

    float a[2];
    a[0] = (tb     < len) ? g_a[base + tb]     : 0.f;
    a[1] = (tb + 1 < len) ? g_a[base + tb + 1] : 0.f;

    double pair = (double)a[0] + (double)a[1];
    double v = pair;
    int lane = tid & 31, wid = tid >> 5;
#pragma unroll
    for (int off = 1; off < 32; off <<= 1) {
        double n = __shfl_up_sync(0xffffffffu, v, off);
        if (lane >= off) v += n;
    }
    if (lane == 31) wt[wid] = v;
    __syncthreads();
    if (tid == 0) {
        double run = 0.0;
#pragma unroll
        for (int w = 0; w < 4; ++w) { wo[w] = run; run += wt[w]; }
    }
    __syncthreads();

    if (tb >= len) return;             // dead pair: nothing downstream reads it

    double excl0 = g_coff[blk] + wo[wid] + (v - pair);
    double C0 = excl0 + (double)a[0];
    double C1 = C0 + (double)a[1];
    double Ce[2] = {excl0, C0};
    double Ci[2] = {C0, C1};

    float w1v[2], w2v[2];
#pragma unroll
    for (int e = 0; e < 2; ++e) {
        int t = tb + e;
        double fp = floor(Ce[e]);
        double fc = floor(Ci[e]);
        float af = a[e];
        float w1, w2 = 0.f;
        if (fc > fp) {                      // fire (alpha<1 => fc == fp+1)
            float aaccf = (float)(Ce[e] - fp);   // reference-style f32 aacc
            w1 = 1.0f - aaccf;
            w2 = af - w1;
            g_firepos[base + (int)fp] = t;
        } else {
            w1 = af;
        }
        w1v[e] = w1; w2v[e] = w2;
    }
    *(float2*)(g_wmain  + base + tb) = make_float2(w1v[0], w1v[1]);
    *(float2*)(g_wspill + base + tb) = make_float2(w2v[0], w2v[1]);
}

// ============================================================
// kD: output row (b,j) = segmented weighted sum, same t-order as reference.
// grid (SS, BB) x 192 threads (one float4 column per thread).
// ============================================================
__global__ void kD(const float* __restrict__ x, float* __restrict__ out) {
    int j = blockIdx.x, b = blockIdx.y;
    int i = threadIdx.x;                  // 0..191
    float4* o4 = (float4*)out + (size_t)(b * SS + j) * DD4 + i;
    int F = g_F[b];
    if (j >= F) { *o4 = make_float4(0.f, 0.f, 0.f, 0.f); return; }

    int p1 = g_firepos[b * SS + j];
    int p0 = (j == 0) ? 0 : g_firepos[b * SS + j - 1];
    const float4* x4 = (const float4*)x + (size_t)b * SS * DD4 + i;

    float4 acc = make_float4(0.f, 0.f, 0.f, 0.f);
    int t = p0;
    if (j > 0) {                          // spill a2*h from previous fire step
        float w = g_wspill[b * SS + p0];
        float4 h = __ldg(x4 + (size_t)p0 * DD4);
        acc.x = w * h.x; acc.y = w * h.y; acc.z = w * h.z; acc.w = w * h.w;
        t = p0 + 1;
    }
#pragma unroll 4
    for (; t <= p1; ++t) {                // interior a*h ... then a1*h at fire
        float w = g_wmain[b * SS + t];
        float4 h = __ldg(x4 + (size_t)t * DD4);
        acc.x += w * h.x; acc.y += w * h.y; acc.z += w * h.z; acc.w += w * h.w;
    }
    *o4 = acc;
}

// ============================================================
extern "C" void kernel_launch(void* const* d_in, const int* in_sizes, int n_in,
                              void* d_out, int out_size) {
    const float* x      = (const float*)d_in[0];   // encoder_outputs (B,S,D)
    const int*   lens   = (const int*)  d_in[1];   // encoder_lens (B,)
    const float* conv_w = (const float*)d_in[2];   // (D,D,3)
    const float* conv_b = (const float*)d_in[3];   // (D,)
    const float* lin_w  = (const float*)d_in[4];   // (1,D)
    const float* lin_b  = (const float*)d_in[5];   // (1,)
    float* out = (float*)d_out;
    float* lens_out = (out_size >= BB * SS * DD + BB) ? out + (size_t)BB * SS * DD
                                                      : nullptr;

    kA1<<<dim3(ROW3 / 256, NCHUNK), 256>>>(conv_w, lin_w);
    kA2<<<ROW3 / 256, 256>>>(conv_b, lin_w, lin_b);
    kB<<<BB * SS / 8, 256>>>(x, lens);
    kC1<<<BB * CH, 256>>>(lens);
    kC2<<<1, 32>>>(lens_out);
    kC3<<<BB * CH, 128>>>(lens);
    kD<<<dim3(SS, BB), 192>>>(x, out);
}